// round 15
// baseline (speedup 1.0000x reference)
#include <cuda_runtime.h>
#include <cuda_fp16.h>
#include <cstdint>

// Problem constants
#define TT   512      // seq len
#define HH   128      // hidden
#define BB   2048     // batch
#define NB   16       // batch per CTA (split into halves of 8)
#define NW   8        // warps per CTA
#define NTH  (NW*32)  // 256 threads
#define NCTA (BB/NB)  // 128 CTAs
#define KPAD 136      // h-buffer row stride in fp16 elems (128 + 8 pad)

// SMEM layout (bytes)
#define SM_XS   0                          // x transposed [T][NB] f32 : 32768
#define SM_HA   32768                      // h half A [8][KPAD] fp16 : 2176 -> 2304
#define SM_HB   (SM_HA + 2304)             // h half B
#define SM_RED  (SM_HB + 2304)             // per-warp MLP partials: NW*NB f32 = 512
#define SM_TOTAL (SM_RED + 512)

__device__ __forceinline__ __half2 tanh2(__half2 x) {
    uint32_t xi = *reinterpret_cast<uint32_t*>(&x), yi;
    asm("tanh.approx.f16x2 %0, %1;" : "=r"(yi) : "r"(xi));
    return *reinterpret_cast<__half2*>(&yi);
}
__device__ __forceinline__ uint32_t packhf(float lo, float hi) {
    __half2 v = __floats2half2_rn(lo, hi);
    return *reinterpret_cast<uint32_t*>(&v);
}
__device__ __forceinline__ void mma16816(
    float& d0, float& d1, float& d2, float& d3,
    uint32_t a0, uint32_t a1, uint32_t a2, uint32_t a3,
    uint32_t b0, uint32_t b1)
{
    asm volatile(
        "mma.sync.aligned.m16n8k16.row.col.f32.f16.f16.f32 "
        "{%0,%1,%2,%3}, {%4,%5,%6,%7}, {%8,%9}, {%0,%1,%2,%3};"
        : "+f"(d0), "+f"(d1), "+f"(d2), "+f"(d3)
        : "r"(a0), "r"(a1), "r"(a2), "r"(a3), "r"(b0), "r"(b1));
}

// One n8 half. Accumulators initialized with x*W_ih + bias (i/f/o rows
// pre-scaled by 0.5), then MMA accumulates W_hh @ h on top.
__device__ __forceinline__ void mma_half(
    const char* __restrict__ hb, const uint32_t (&Afr)[4][8][4],
    float (&acc)[4][4], const float* __restrict__ xsp,
    const float (&wg4)[2][4], const float (&bg4)[2][4],
    int lq, int lr)
{
    const float xv0 = xsp[2 * lr];
    const float xv1 = xsp[2 * lr + 1];
#pragma unroll
    for (int g = 0; g < 4; g++)
#pragma unroll
        for (int r = 0; r < 2; r++) {
            acc[g][2 * r + 0] = fmaf(xv0, wg4[r][g], bg4[r][g]);
            acc[g][2 * r + 1] = fmaf(xv1, wg4[r][g], bg4[r][g]);
        }
#pragma unroll
    for (int kc = 0; kc < 8; kc++) {
        const int k0 = kc * 16 + 2 * lr;
        uint32_t b0 = *(const uint32_t*)(hb + (lq * KPAD + k0) * 2);
        uint32_t b1 = *(const uint32_t*)(hb + (lq * KPAD + k0 + 8) * 2);
#pragma unroll
        for (int g = 0; g < 4; g++)
            mma16816(acc[g][0], acc[g][1], acc[g][2], acc[g][3],
                     Afr[g][kc][0], Afr[g][kc][1], Afr[g][kc][2], Afr[g][kc][3],
                     b0, b1);
    }
}

// Epilogue for one half, fp16x2 nonlinearities (pair over cc=0,1):
// i/f/o preacts pre-scaled 0.5 -> sigmoid = hfma2(0.5, tanh2, 0.5).
// c stays in f32. h written as fp16 to hb; pair kept in hsv[r] (half2).
__device__ __forceinline__ void epi_half(
    const float (&acc)[4][4], float (&cst)[2][2], __half2 (&hsv)[2],
    char* __restrict__ hb, int w, int lq, int lr)
{
    const __half2 h05 = __floats2half2_rn(0.5f, 0.5f);
    const int nl0 = 2 * lr, nl1 = 2 * lr + 1;
#pragma unroll
    for (int r = 0; r < 2; r++) {
        const int j0 = 2 * r, j1 = 2 * r + 1;
        __half2 ti = tanh2(__floats2half2_rn(acc[0][j0], acc[0][j1]));
        __half2 tf = tanh2(__floats2half2_rn(acc[1][j0], acc[1][j1]));
        __half2 tg = tanh2(__floats2half2_rn(acc[2][j0], acc[2][j1]));
        __half2 to = tanh2(__floats2half2_rn(acc[3][j0], acc[3][j1]));
        __half2 ii = __hfma2(h05, ti, h05);
        __half2 ff = __hfma2(h05, tf, h05);
        __half2 oo = __hfma2(h05, to, h05);
        float c0 = fmaf(__low2float(ff),  cst[r][0],
                        __low2float(ii)  * __low2float(tg));
        float c1 = fmaf(__high2float(ff), cst[r][1],
                        __high2float(ii) * __high2float(tg));
        cst[r][0] = c0;
        cst[r][1] = c1;
        __half2 tc = tanh2(__floats2half2_rn(c0, c1));
        __half2 h2 = __hmul2(oo, tc);
        hsv[r] = h2;
        const int hid = 16 * w + lq + 8 * r;
        *(__half*)(hb + (nl0 * KPAD + hid) * 2) = __low2half(h2);
        *(__half*)(hb + (nl1 * KPAD + hid) * 2) = __high2half(h2);
    }
}

__global__ void __launch_bounds__(NTH, 1) lstm_hmma_kernel(
    const float* __restrict__ x,    const float* __restrict__ hx0,
    const float* __restrict__ cx0,  const float* __restrict__ Wih,
    const float* __restrict__ Whh,  const float* __restrict__ bih,
    const float* __restrict__ bhh,  const float* __restrict__ Wmlp,
    const float* __restrict__ bmlp, float* __restrict__ out)
{
    extern __shared__ char smem[];
    const int tid  = threadIdx.x;
    const int w    = tid >> 5;          // warp owns hid [16w, 16w+16)
    const int l    = tid & 31;
    const int b0   = blockIdx.x * NB;
    const int lq   = l >> 2;            // 0..7
    const int lr   = l & 3;             // 0..3

    // ---------- stage x transposed: xs[t][n] ----------
    float* xs = (float*)(smem + SM_XS);
    for (int idx = tid; idx < NB * TT; idx += NTH) {
        int n = idx >> 9, t = idx & (TT - 1);
        xs[t * NB + n] = x[(size_t)(b0 + n) * TT + t];
    }
    // ---------- stage h0 (fp16): half A rows n 0..7, half B rows n 8..15 ----------
    for (int idx = tid; idx < NB * HH; idx += NTH) {
        int n = idx >> 7, k = idx & 127;
        char* hb = smem + ((n < 8) ? SM_HA : SM_HB);
        ((__half*)hb)[(n & 7) * KPAD + k] =
            __float2half(hx0[(size_t)(b0 + n) * HH + k]);
    }

    // ---------- W_hh A-fragments (fp16) in registers; i/f/o rows scaled 0.5 ----------
    uint32_t Afr[4][8][4];
#pragma unroll
    for (int g = 0; g < 4; g++) {
        const float sc = (g == 2) ? 1.0f : 0.5f;   // gate order i,f,g,o
        const int r0 = g * 128 + 16 * w + lq;
#pragma unroll
        for (int kc = 0; kc < 8; kc++) {
            const int c0 = kc * 16 + 2 * lr;
            const float* p0 = Whh + (size_t)r0 * HH + c0;
            const float* p1 = Whh + (size_t)(r0 + 8) * HH + c0;
            Afr[g][kc][0] = packhf(sc * p0[0], sc * p0[1]);
            Afr[g][kc][1] = packhf(sc * p1[0], sc * p1[1]);
            Afr[g][kc][2] = packhf(sc * p0[8], sc * p0[9]);
            Afr[g][kc][3] = packhf(sc * p1[8], sc * p1[9]);
        }
    }

    // ---------- per-thread gate constants (i/f/o scaled by 0.5) ----------
    float wg4[2][4], bg4[2][4], pm[2];
#pragma unroll
    for (int r = 0; r < 2; r++) {
        const int hid = 16 * w + lq + 8 * r;
#pragma unroll
        for (int g = 0; g < 4; g++) {
            const float sc = (g == 2) ? 1.0f : 0.5f;
            wg4[r][g] = sc * Wih[g * 128 + hid];
            bg4[r][g] = sc * (bih[g * 128 + hid] + bhh[g * 128 + hid]);
        }
        pm[r] = Wmlp[hid];
    }

    // ---------- c state per half ----------
    float cstA[2][2], cstB[2][2];
    __half2 hsvA[2], hsvB[2];
#pragma unroll
    for (int r = 0; r < 2; r++)
#pragma unroll
        for (int cc = 0; cc < 2; cc++) {
            const int hid = 16 * w + lq + 8 * r;
            const int nl = 2 * lr + cc;
            cstA[r][cc] = cx0[(size_t)(b0 + nl) * HH + hid];
            cstB[r][cc] = cx0[(size_t)(b0 + 8 + nl) * HH + hid];
        }

    char* hbA = smem + SM_HA;
    char* hbB = smem + SM_HB;
    __syncthreads();

    float accA[4][4], accB[4][4];

    // ---------- software-pipelined recurrence ----------
    // phase1(t): MMA_A(t) || epi_B(t-1)   phase2(t): MMA_B(t) || epi_A(t)
    mma_half(hbA, Afr, accA, xs, wg4, bg4, lq, lr);
    __syncthreads();
    mma_half(hbB, Afr, accB, xs + 8, wg4, bg4, lq, lr);
    epi_half(accA, cstA, hsvA, hbA, w, lq, lr);
    __syncthreads();

#pragma unroll 1
    for (int t = 1; t < TT; t++) {
        // phase1: tensor work for half A overlaps fp16x2 epilogue of half B
        mma_half(hbA, Afr, accA, xs + t * NB, wg4, bg4, lq, lr);
        epi_half(accB, cstB, hsvB, hbB, w, lq, lr);
        __syncthreads();
        // phase2: tensor work for half B overlaps fp16x2 epilogue of half A
        mma_half(hbB, Afr, accB, xs + t * NB + 8, wg4, bg4, lq, lr);
        epi_half(accA, cstA, hsvA, hbA, w, lq, lr);
        __syncthreads();
    }
    // tail: finish half B at t = TT-1
    epi_half(accB, cstB, hsvB, hbB, w, lq, lr);

    // ---------- final MLP + sigmoid ----------
    float* red = (float*)(smem + SM_RED);
#pragma unroll
    for (int half = 0; half < 2; half++) {
        const __half2* hs = half ? hsvB : hsvA;
#pragma unroll
        for (int cc = 0; cc < 2; cc++) {
            float h0 = cc ? __high2float(hs[0]) : __low2float(hs[0]);
            float h1 = cc ? __high2float(hs[1]) : __low2float(hs[1]);
            float v = fmaf(h0, pm[0], h1 * pm[1]);
            // reduce over the 8 lanes (lq = lane bits 2..4) sharing this n
            v += __shfl_xor_sync(0xffffffffu, v, 4);
            v += __shfl_xor_sync(0xffffffffu, v, 8);
            v += __shfl_xor_sync(0xffffffffu, v, 16);
            if (lq == 0) red[w * NB + 8 * half + 2 * lr + cc] = v;
        }
    }
    __syncthreads();
    if (tid < NB) {
        float logit = bmlp[0];
#pragma unroll
        for (int wq = 0; wq < NW; wq++) logit += red[wq * NB + tid];
        out[b0 + tid] = 1.0f / (1.0f + __expf(-logit));
    }
}

extern "C" void kernel_launch(void* const* d_in, const int* in_sizes, int n_in,
                              void* d_out, int out_size) {
    (void)in_sizes; (void)n_in; (void)out_size;
    const float* x    = (const float*)d_in[0];
    const float* hx0  = (const float*)d_in[1];
    const float* cx0  = (const float*)d_in[2];
    const float* Wih  = (const float*)d_in[3];
    const float* Whh  = (const float*)d_in[4];
    const float* bih  = (const float*)d_in[5];
    const float* bhh  = (const float*)d_in[6];
    const float* Wmlp = (const float*)d_in[7];
    const float* bmlp = (const float*)d_in[8];
    float* out = (float*)d_out;

    cudaFuncSetAttribute(lstm_hmma_kernel,
                         cudaFuncAttributeMaxDynamicSharedMemorySize, SM_TOTAL);
    lstm_hmma_kernel<<<NCTA, NTH, SM_TOTAL>>>(
        x, hx0, cx0, Wih, Whh, bih, bhh, Wmlp, bmlp, out);
}